// round 14
// baseline (speedup 1.0000x reference)
#include <cuda_runtime.h>
#include <cuda_bf16.h>

// ---------------- problem dims ----------------
#define Bn 256
#define Sn 336
#define Fn 8
#define Hn 512
#define Pn 96

// ---------------- partition: 256 blocks, 2 per SM ----------------
#define GB   2                 // batch halves
#define GHN  128               // col groups (4 cols each)
#define NBLK (GB * GHN)        // 256 blocks
#define BT   128               // batches per block
#define CT   4                 // h-cols per block
#define NR   16                // gate rows per block (4 gates x 4 cols)
#define KCH  64                // k elements per chunk
#define NCH  (Hn / KCH)        // 8
#define NTH  256

// plane strides (bf16 units); stride*2 mod 128 == 16 -> ldmatrix 8-row
// phases tile all 32 banks
#define WPS 520                // W plane row stride (1040 B)
#define BPS 72                 // h plane row stride (144 B)

#define W_HALF (NR * WPS)      // 8320 bf16 per W plane
#define B_HALF (BT * BPS)      // 9216 bf16 per h plane per buffer
#define BF_TOTAL (2 * W_HALF + 4 * B_HALF)   // 53504 bf16 = 107008 B
#define XS_F   (BT * Fn)       // 1024
#define SMEM_BYTES (BF_TOTAL * 2 + (XS_F + NR + NR * Fn) * 4)   // 111680

// ---------------- device scratch ----------------
__device__ __nv_bfloat16 g_h_hi[2][Bn][Hn];
__device__ __nv_bfloat16 g_h_lo[2][Bn][Hn];
__device__ unsigned g_bar_count;
__device__ unsigned g_bar_gen;
__device__ unsigned g_cnt[2][8];     // monotonic producer counters [half][chunk group]

// ---------------- helpers ----------------
__device__ __forceinline__ void cp_async16(void* dst_sh, const void* src) {
    unsigned d = (unsigned)__cvta_generic_to_shared(dst_sh);
    asm volatile("cp.async.ca.shared.global [%0], [%1], 16;\n" :: "r"(d), "l"(src));
}
__device__ __forceinline__ void cp_commit() {
    asm volatile("cp.async.commit_group;\n" ::: "memory");
}
template <int N>
__device__ __forceinline__ void cp_wait() {
    asm volatile("cp.async.wait_group %0;\n" :: "n"(N) : "memory");
}

__device__ __forceinline__ float sigf(float x) { return 1.0f / (1.0f + __expf(-x)); }
__device__ __forceinline__ float tanh_fast(float x) {
    return 2.0f / (1.0f + __expf(-2.0f * x)) - 1.0f;
}
__device__ __forceinline__ void split2(float x, __nv_bfloat16& h, __nv_bfloat16& l) {
    h = __float2bfloat16(x);
    l = __float2bfloat16(x - __bfloat162float(h));
}

__device__ __forceinline__ void mma_bf16(float d[4], const unsigned a[4],
                                         const unsigned b0, const unsigned b1) {
    asm volatile(
        "mma.sync.aligned.m16n8k16.row.col.f32.bf16.bf16.f32 "
        "{%0,%1,%2,%3},{%4,%5,%6,%7},{%8,%9},{%0,%1,%2,%3};"
        : "+f"(d[0]), "+f"(d[1]), "+f"(d[2]), "+f"(d[3])
        : "r"(a[0]), "r"(a[1]), "r"(a[2]), "r"(a[3]), "r"(b0), "r"(b1));
}
__device__ __forceinline__ void ldsm_x4(unsigned a[4], unsigned addr) {
    asm volatile("ldmatrix.sync.aligned.m8n8.x4.shared.b16 {%0,%1,%2,%3},[%4];"
                 : "=r"(a[0]), "=r"(a[1]), "=r"(a[2]), "=r"(a[3]) : "r"(addr));
}
__device__ __forceinline__ void ldsm_x2(unsigned b[2], unsigned addr) {
    asm volatile("ldmatrix.sync.aligned.m8n8.x2.shared.b16 {%0,%1},[%2];"
                 : "=r"(b[0]), "=r"(b[1]) : "r"(addr));
}

__device__ __forceinline__ void poll_cnt(int h, int cg, unsigned target) {
    if (target == 0u) return;
    const unsigned* a = &g_cnt[h][cg];
    unsigned v;
    do {
        asm volatile("ld.acquire.gpu.u32 %0, [%1];" : "=r"(v) : "l"(a) : "memory");
    } while (v < target);
}

// full grid barrier (used ONCE after init)
__device__ __forceinline__ void grid_barrier() {
    __syncthreads();
    if (threadIdx.x == 0) {
        unsigned gen;
        asm volatile("ld.acquire.gpu.u32 %0, [%1];" : "=r"(gen) : "l"(&g_bar_gen) : "memory");
        unsigned prev;
        asm volatile("atom.add.release.gpu.u32 %0, [%1], 1;"
                     : "=r"(prev) : "l"(&g_bar_count) : "memory");
        if (prev == NBLK - 1) {
            asm volatile("st.relaxed.gpu.u32 [%0], %1;" :: "l"(&g_bar_count), "r"(0u) : "memory");
            asm volatile("st.release.gpu.u32 [%0], %1;" :: "l"(&g_bar_gen), "r"(gen + 1u) : "memory");
        } else {
            unsigned cur;
            do {
                asm volatile("ld.acquire.gpu.u32 %0, [%1];" : "=r"(cur) : "l"(&g_bar_gen) : "memory");
            } while (cur == gen);
        }
    }
    __syncthreads();
}

// stage 16x512 weight slice, split hi/lo planes.
// smem row mapping: r = (gate>>1)*8 + col*2 + (gate&1)
//   -> ldsm frag rows (cc, cc+8) give (gate ga, gate ga+2) of col cc>>1, ga=cc&1
__device__ __forceinline__ void stage_weights(__nv_bfloat16* Whi, __nv_bfloat16* Wlo,
                                              const float* W, int colbase, int tid) {
    const int r    = tid >> 4;          // 0..15
    const int seg  = tid & 15;          // 32-col segment
    const int gate = ((r >> 3) << 1) | (r & 1);
    const int col  = (r & 7) >> 1;
    const float* src = W + (size_t)(gate * Hn + colbase + col) * Hn + seg * 32;
    __nv_bfloat16* dh = Whi + r * WPS + seg * 32;
    __nv_bfloat16* dl = Wlo + r * WPS + seg * 32;
    #pragma unroll
    for (int j = 0; j < 8; j++) {
        const float4 v = ((const float4*)src)[j];
        split2(v.x, dh[4 * j + 0], dl[4 * j + 0]);
        split2(v.y, dh[4 * j + 1], dl[4 * j + 1]);
        split2(v.z, dh[4 * j + 2], dl[4 * j + 2]);
        split2(v.w, dh[4 * j + 3], dl[4 * j + 3]);
    }
}

// ---------------- kernel ----------------
__global__ void __launch_bounds__(NTH, 2)
lstm_kernel(const float* __restrict__ x_enc,
            const float* __restrict__ enc_Wih,
            const float* __restrict__ enc_Whh,
            const float* __restrict__ enc_b,
            const float* __restrict__ dec_Wih,
            const float* __restrict__ dec_Whh,
            const float* __restrict__ dec_b,
            const float* __restrict__ lin_W,
            const float* __restrict__ lin_b,
            float* __restrict__ out)
{
    extern __shared__ __nv_bfloat16 smem_bf[];
    __nv_bfloat16* Whi = smem_bf;                  // [NR][WPS]
    __nv_bfloat16* Wlo = Whi + W_HALF;             // [NR][WPS]
    __nv_bfloat16* Bsh = Wlo + W_HALF;             // [2 buf][2 plane][BT][BPS]
    float* x_sh    = (float*)(smem_bf + BF_TOTAL); // [BT][Fn]
    float* bias_sh = x_sh + XS_F;                  // [16] (gate*4+col)
    float* wih_sh  = bias_sh + NR;                 // [16][Fn]

    const int tid     = threadIdx.x;
    const int bid     = blockIdx.x;
    const int gh      = bid % GHN;      // 0..127
    const int gbx     = bid / GHN;      // 0..1
    const int bstart  = gbx * BT;
    const int colbase = gh * CT;
    const int mygrp   = gh >> 4;        // chunk group this block produces (0..7)

    const int w    = tid >> 5;          // warp 0..7 (batches w*16..w*16+15)
    const int lane = tid & 31;
    const int cc   = lane >> 2;         // frag row id 0..7
    const int q    = lane & 3;
    const int col  = cc >> 1;           // 0..3
    const int ga   = cc & 1;            // this lane's low gate (0 or 1)

    // ---- stage encoder weights + bias + Wih ----
    stage_weights(Whi, Wlo, enc_Whh, colbase, tid);
    if (tid < NR) {
        const int g2 = tid >> 2, c2 = tid & 3;
        bias_sh[tid] = enc_b[g2 * Hn + colbase + c2];
        #pragma unroll
        for (int k = 0; k < Fn; k++)
            wih_sh[tid * Fn + k] = enc_Wih[(size_t)(g2 * Hn + colbase + c2) * Fn + k];
    }

    // ---- per-launch re-init of global scratch + counters ----
    {
        const int per = (Bn * Hn) / NBLK;   // 512
        __nv_bfloat16* zh = &g_h_hi[1][0][0] + bid * per;
        __nv_bfloat16* zl = &g_h_lo[1][0][0] + bid * per;
        for (int j = tid; j < per; j += NTH) { zh[j] = __nv_bfloat16(0.f); zl[j] = __nv_bfloat16(0.f); }
        const int pero = (Bn * Pn) / NBLK;  // 96
        const int base = bid * pero;
        for (int j = tid; j < pero; j += NTH) out[base + j] = 0.0f;
        if (bid == 0 && tid < 16)
            asm volatile("st.relaxed.gpu.u32 [%0], %1;"
                         :: "l"(&g_cnt[tid >> 3][tid & 7]), "r"(0u) : "memory");
    }

    float creg[4] = {0.f, 0.f, 0.f, 0.f};
    const float lw = lin_W[colbase + col];
    const float lb = lin_b[0];

    // ---- ldmatrix base addresses (byte, shared space) ----
    unsigned aBase[2];   // [plane] (single M16 tile)
    {
        const int mat  = lane >> 3;
        const int mrow = ((mat & 1) << 3) + (lane & 7);
        const int kb   = (mat >> 1) * 16;
        aBase[0] = (unsigned)__cvta_generic_to_shared(Whi) + (unsigned)(mrow * WPS) * 2 + kb;
        aBase[1] = (unsigned)__cvta_generic_to_shared(Wlo) + (unsigned)(mrow * WPS) * 2 + kb;
    }
    unsigned bBase[2][2];   // [tn][plane], buffer 0
    {
        const int l16  = lane & 15;
        const int nrow = l16 & 7;
        const int kb   = (l16 >> 3) * 16;
        const unsigned bA = (unsigned)__cvta_generic_to_shared(Bsh);
        #pragma unroll
        for (int tn = 0; tn < 2; tn++) {
            #pragma unroll
            for (int p = 0; p < 2; p++)
                bBase[tn][p] = bA + (unsigned)(p * B_HALF + (w * 16 + tn * 8 + nrow) * BPS) * 2 + kb;
        }
    }

    grid_barrier();   // zeros + counters + weights visible (only full barrier)

    for (int s = 0; s < Sn + Pn; s++) {
        const bool enc = (s < Sn);
        const unsigned tgt = 16u * (unsigned)s;
        const __nv_bfloat16* hprev_hi = &g_h_hi[(s + 1) & 1][0][0];
        const __nv_bfloat16* hprev_lo = &g_h_lo[(s + 1) & 1][0][0];
        __nv_bfloat16*       hnext_hi = &g_h_hi[s & 1][0][0];
        __nv_bfloat16*       hnext_lo = &g_h_lo[s & 1][0][0];

        // ---- encoder -> decoder weight swap (once, block-local) ----
        if (s == Sn) {
            __syncthreads();
            stage_weights(Whi, Wlo, dec_Whh, colbase, tid);
            if (tid < NR) {
                const int g2 = tid >> 2, c2 = tid & 3;
                bias_sh[tid] = dec_b[g2 * Hn + colbase + c2];
                wih_sh[tid * Fn] = dec_Wih[g2 * Hn + colbase + c2];
            }
            __syncthreads();
        }

        // ---- wait for chunk-0 producers, prefetch chunk 0 ----
        poll_cnt(gbx, 0, tgt);
        {
            #pragma unroll
            for (int j = 0; j < 8; j++) {
                const int idx   = j * NTH + tid;
                const int plane = idx >> 10;
                const int rem   = idx & 1023;
                const int row   = rem >> 3;
                const int seg   = rem & 7;
                const __nv_bfloat16* sp = plane ? hprev_lo : hprev_hi;
                cp_async16(Bsh + plane * B_HALF + row * BPS + seg * 8,
                           sp + (size_t)(bstart + row) * Hn + seg * 8);
            }
            cp_commit();
        }

        // ---- accumulator init: bias + Wih*x ----
        // d[tn][j]   = gate ga,   col, batches (w*16+tn*8+2q+j)
        // d[tn][2+j] = gate ga+2, same
        float d[2][4];
        const float blo = bias_sh[ga * 4 + col];
        const float bhi = bias_sh[(ga + 2) * 4 + col];
        if (enc) {
            {
                const int b = tid >> 1, part = tid & 1;
                const float4 v = *(const float4*)(x_enc +
                        ((size_t)(bstart + b) * Sn + s) * Fn + part * 4);
                *((float4*)&x_sh[b * Fn + part * 4]) = v;
            }
            __syncthreads();
            #pragma unroll
            for (int tn = 0; tn < 2; tn++) {
                #pragma unroll
                for (int j = 0; j < 2; j++) {
                    const int nb = w * 16 + tn * 8 + 2 * q + j;
                    float tl = blo, th = bhi;
                    #pragma unroll
                    for (int k = 0; k < Fn; k++) {
                        const float xv = x_sh[nb * Fn + k];
                        tl = fmaf(xv, wih_sh[(ga * 4 + col) * Fn + k], tl);
                        th = fmaf(xv, wih_sh[((ga + 2) * 4 + col) * Fn + k], th);
                    }
                    d[tn][j] = tl; d[tn][2 + j] = th;
                }
            }
        } else {
            // y feedback needs ALL producers of step s-1 done
            #pragma unroll
            for (int cg = 1; cg < 8; cg++) poll_cnt(gbx, cg, tgt);
            const float wl = wih_sh[(ga * 4 + col) * Fn];
            const float wh = wih_sh[((ga + 2) * 4 + col) * Fn];
            #pragma unroll
            for (int tn = 0; tn < 2; tn++) {
                #pragma unroll
                for (int j = 0; j < 2; j++) {
                    const int b = bstart + w * 16 + tn * 8 + 2 * q + j;
                    const float xv = (s == Sn)
                        ? x_enc[((size_t)b * Sn + (Sn - 1)) * Fn + 3]
                        : out[(size_t)b * Pn + (s - Sn - 1)];
                    d[tn][j]     = fmaf(xv, wl, blo);
                    d[tn][2 + j] = fmaf(xv, wh, bhi);
                }
            }
        }

        // ---- GEMM over K=512, 8 chunks, double-buffered ----
        for (int ci = 0; ci < NCH; ci++) {
            __syncthreads();
            if (ci + 1 < NCH) {
                poll_cnt(gbx, ci + 1, tgt);
                __nv_bfloat16* dst = Bsh + ((ci + 1) & 1) * (2 * B_HALF);
                const int koff = (ci + 1) * KCH;
                #pragma unroll
                for (int j = 0; j < 8; j++) {
                    const int idx   = j * NTH + tid;
                    const int plane = idx >> 10;
                    const int rem   = idx & 1023;
                    const int row   = rem >> 3;
                    const int seg   = rem & 7;
                    const __nv_bfloat16* sp = plane ? hprev_lo : hprev_hi;
                    cp_async16(dst + plane * B_HALF + row * BPS + seg * 8,
                               sp + (size_t)(bstart + row) * Hn + koff + seg * 8);
                }
                cp_commit();
                cp_wait<1>();
            } else {
                cp_wait<0>();
            }
            __syncthreads();

            const unsigned bufOff = (unsigned)((ci & 1) * (2 * B_HALF)) * 2;
            const unsigned kA0    = (unsigned)(ci * KCH) * 2;
            #pragma unroll
            for (int kt = 0; kt < KCH / 16; kt++) {
                const unsigned kbA = kA0 + (unsigned)kt * 32u;
                const unsigned kbB = bufOff + (unsigned)kt * 32u;

                unsigned a_hi[4], a_lo[4];
                ldsm_x4(a_hi, aBase[0] + kbA);
                ldsm_x4(a_lo, aBase[1] + kbA);
                unsigned b_hi[2][2], b_lo[2][2];
                #pragma unroll
                for (int tn = 0; tn < 2; tn++) {
                    ldsm_x2(b_hi[tn], bBase[tn][0] + kbB);
                    ldsm_x2(b_lo[tn], bBase[tn][1] + kbB);
                }
                #pragma unroll
                for (int tn = 0; tn < 2; tn++) {
                    mma_bf16(d[tn], a_hi, b_hi[tn][0], b_hi[tn][1]);
                    mma_bf16(d[tn], a_hi, b_lo[tn][0], b_lo[tn][1]);
                    mma_bf16(d[tn], a_lo, b_hi[tn][0], b_hi[tn][1]);
                }
            }
        }

        // ---- epilogue: pair exchange (lane^4 has the other gate pair) ----
        float pd[2][4];
        #pragma unroll
        for (int tn = 0; tn < 2; tn++)
            #pragma unroll
            for (int r = 0; r < 4; r++)
                pd[tn][r] = __shfl_xor_sync(0xffffffffu, d[tn][r], 4);

        float hv[4];
        #pragma unroll
        for (int tn = 0; tn < 2; tn++) {
            #pragma unroll
            for (int j = 0; j < 2; j++) {
                const int idx = 2 * tn + j;
                const float vi = (ga == 0) ? d[tn][j]      : pd[tn][j];
                const float vf = (ga == 0) ? pd[tn][j]     : d[tn][j];
                const float vg = (ga == 0) ? d[tn][2 + j]  : pd[tn][2 + j];
                const float vo = (ga == 0) ? pd[tn][2 + j] : d[tn][2 + j];
                const float cn = fmaf(sigf(vf), creg[idx], sigf(vi) * tanh_fast(vg));
                creg[idx] = cn;
                const float h = sigf(vo) * tanh_fast(cn);
                hv[idx] = h;
                if (ga == 0) {
                    const int b = bstart + w * 16 + tn * 8 + 2 * q + j;
                    __nv_bfloat16 hh, hl;
                    split2(h, hh, hl);
                    hnext_hi[(size_t)b * Hn + colbase + col] = hh;
                    hnext_lo[(size_t)b * Hn + colbase + col] = hl;
                }
            }
        }

        // ---- decoder output: y = h @ lin_W^T + lin_b ----
        if (!enc) {
            float py[4];
            #pragma unroll
            for (int idx = 0; idx < 4; idx++) py[idx] = hv[idx] * lw;
            // sum over the 4 cols: lanes cc, cc^2, cc^4 (xor 8, 16) keep ga fixed
            #pragma unroll
            for (int idx = 0; idx < 4; idx++) {
                py[idx] += __shfl_xor_sync(0xffffffffu, py[idx], 8);
                py[idx] += __shfl_xor_sync(0xffffffffu, py[idx], 16);
            }
            if (cc == 0) {
                const float add = (gh == 0) ? lb : 0.0f;
                #pragma unroll
                for (int tn = 0; tn < 2; tn++)
                    #pragma unroll
                    for (int j = 0; j < 2; j++) {
                        const int b = bstart + w * 16 + tn * 8 + 2 * q + j;
                        atomicAdd(&out[(size_t)b * Pn + (s - Sn)],
                                  py[2 * tn + j] + add);
                    }
            }
        }

        // ---- publish this block's columns for step s ----
        __syncthreads();
        if (tid == 0) {
            unsigned dummy;
            asm volatile("atom.add.release.gpu.u32 %0, [%1], %2;"
                         : "=r"(dummy) : "l"(&g_cnt[gbx][mygrp]), "r"(1u) : "memory");
        }
    }
}

// ---------------- launch ----------------
extern "C" void kernel_launch(void* const* d_in, const int* in_sizes, int n_in,
                              void* d_out, int out_size)
{
    const float* x_enc   = (const float*)d_in[0];
    const float* enc_Wih = (const float*)d_in[1];
    const float* enc_Whh = (const float*)d_in[2];
    const float* enc_b   = (const float*)d_in[3];
    const float* dec_Wih = (const float*)d_in[4];
    const float* dec_Whh = (const float*)d_in[5];
    const float* dec_b   = (const float*)d_in[6];
    const float* lin_W   = (const float*)d_in[7];
    const float* lin_b   = (const float*)d_in[8];
    float* out = (float*)d_out;

    cudaFuncSetAttribute(lstm_kernel,
                         cudaFuncAttributeMaxDynamicSharedMemorySize, SMEM_BYTES);

    lstm_kernel<<<NBLK, NTH, SMEM_BYTES>>>(x_enc, enc_Wih, enc_Whh, enc_b,
                                           dec_Wih, dec_Whh, dec_b,
                                           lin_W, lin_b, out);
}

// round 16
// speedup vs baseline: 1.1786x; 1.1786x over previous
#include <cuda_runtime.h>
#include <cuda_bf16.h>

// ---------------- problem dims ----------------
#define Bn 256
#define Sn 336
#define Fn 8
#define Hn 512
#define Pn 96

// ---------------- partition (R7/R12 shape) ----------------
#define GB   2
#define GHN  64
#define NBLK (GB * GHN)        // 128 blocks
#define BT   128               // batches per block
#define CT   8                 // h-cols per block
#define NR   32                // gate rows per block

// W plane stride (bf16); stride*2 mod 128 == 16 -> ldmatrix phases tile banks
#define WPS 520
#define W_HALF (NR * WPS)      // 16640 bf16 per plane
#define XS_F   (BT * Fn)
#define SMEM_BYTES (2 * W_HALF * 2 + (XS_F + NR + NR * Fn) * 4)

// ---------------- device scratch ----------------
__device__ __nv_bfloat16 g_h_hi[2][Bn][Hn];
__device__ __nv_bfloat16 g_h_lo[2][Bn][Hn];
__device__ unsigned g_bar_count;
__device__ unsigned g_bar_gen;
__device__ unsigned g_cnt[2][4];     // monotonic producer counters [half][col group]

// ---------------- helpers ----------------
__device__ __forceinline__ float sigf(float x) { return 1.0f / (1.0f + __expf(-x)); }
__device__ __forceinline__ float tanh_fast(float x) {
    return 2.0f / (1.0f + __expf(-2.0f * x)) - 1.0f;
}
__device__ __forceinline__ void split2(float x, __nv_bfloat16& h, __nv_bfloat16& l) {
    h = __float2bfloat16(x);
    l = __float2bfloat16(x - __bfloat162float(h));
}

// m16n8k16 bf16 MMA, fp32 accumulate
__device__ __forceinline__ void mma_bf16(float d[4], const unsigned a[4],
                                         const unsigned b0, const unsigned b1) {
    asm volatile(
        "mma.sync.aligned.m16n8k16.row.col.f32.bf16.bf16.f32 "
        "{%0,%1,%2,%3},{%4,%5,%6,%7},{%8,%9},{%0,%1,%2,%3};"
        : "+f"(d[0]), "+f"(d[1]), "+f"(d[2]), "+f"(d[3])
        : "r"(a[0]), "r"(a[1]), "r"(a[2]), "r"(a[3]), "r"(b0), "r"(b1));
}
__device__ __forceinline__ void ldsm_x4(unsigned a[4], unsigned addr) {
    asm volatile("ldmatrix.sync.aligned.m8n8.x4.shared.b16 {%0,%1,%2,%3},[%4];"
                 : "=r"(a[0]), "=r"(a[1]), "=r"(a[2]), "=r"(a[3]) : "r"(addr));
}
__device__ __forceinline__ unsigned ldg32(const void* p) {
    unsigned v;
    asm volatile("ld.global.b32 %0, [%1];" : "=r"(v) : "l"(p));
    return v;
}

// wait until producer group counter reaches target (acquire)
__device__ __forceinline__ void poll_cnt(int h, int cg, unsigned target) {
    if (target == 0u) return;
    const unsigned* a = &g_cnt[h][cg];
    unsigned v;
    do {
        asm volatile("ld.acquire.gpu.u32 %0, [%1];" : "=r"(v) : "l"(a) : "memory");
    } while (v < target);
}

// full grid barrier (used ONCE after init)
__device__ __forceinline__ void grid_barrier() {
    __syncthreads();
    if (threadIdx.x == 0) {
        unsigned gen;
        asm volatile("ld.acquire.gpu.u32 %0, [%1];" : "=r"(gen) : "l"(&g_bar_gen) : "memory");
        unsigned prev;
        asm volatile("atom.add.release.gpu.u32 %0, [%1], 1;"
                     : "=r"(prev) : "l"(&g_bar_count) : "memory");
        if (prev == NBLK - 1) {
            asm volatile("st.relaxed.gpu.u32 [%0], %1;" :: "l"(&g_bar_count), "r"(0u) : "memory");
            asm volatile("st.release.gpu.u32 [%0], %1;" :: "l"(&g_bar_gen), "r"(gen + 1u) : "memory");
        } else {
            unsigned cur;
            do {
                asm volatile("ld.acquire.gpu.u32 %0, [%1];" : "=r"(cur) : "l"(&g_bar_gen) : "memory");
            } while (cur == gen);
        }
    }
    __syncthreads();
}

// stage 32x512 weight slice split into hi/lo bf16 planes
__device__ __forceinline__ void stage_weights(__nv_bfloat16* Whi, __nv_bfloat16* Wlo,
                                              const float* W, int colbase, int tid) {
    const int r    = tid >> 3;
    const int seg  = tid & 7;
    const int gate = r >> 3;
    const int cc2  = r & 7;
    const float* src = W + (size_t)(gate * Hn + colbase + cc2) * Hn + seg * 64;
    __nv_bfloat16* dh = Whi + r * WPS + seg * 64;
    __nv_bfloat16* dl = Wlo + r * WPS + seg * 64;
    #pragma unroll
    for (int j = 0; j < 16; j++) {
        const float4 v = ((const float4*)src)[j];
        split2(v.x, dh[4 * j + 0], dl[4 * j + 0]);
        split2(v.y, dh[4 * j + 1], dl[4 * j + 1]);
        split2(v.z, dh[4 * j + 2], dl[4 * j + 2]);
        split2(v.w, dh[4 * j + 3], dl[4 * j + 3]);
    }
}

// ---------------- kernel ----------------
__global__ void __launch_bounds__(256, 1)
lstm_kernel(const float* __restrict__ x_enc,
            const float* __restrict__ enc_Wih,
            const float* __restrict__ enc_Whh,
            const float* __restrict__ enc_b,
            const float* __restrict__ dec_Wih,
            const float* __restrict__ dec_Whh,
            const float* __restrict__ dec_b,
            const float* __restrict__ lin_W,
            const float* __restrict__ lin_b,
            float* __restrict__ out)
{
    extern __shared__ __nv_bfloat16 smem_bf[];
    __nv_bfloat16* Whi = smem_bf;                      // [NR][WPS]
    __nv_bfloat16* Wlo = Whi + W_HALF;                 // [NR][WPS]
    float* x_sh    = (float*)(smem_bf + 2 * W_HALF);   // [BT][Fn]
    float* bias_sh = x_sh + XS_F;                      // [NR]
    float* wih_sh  = bias_sh + NR;                     // [NR][Fn]

    const int tid     = threadIdx.x;
    const int bid     = blockIdx.x;
    const int gh      = bid % GHN;
    const int gbx     = bid / GHN;
    const int bstart  = gbx * BT;
    const int colbase = gh * CT;
    const int mygrp   = gh >> 4;

    const int w    = tid >> 5;      // warp 0..7 (batches w*16..w*16+15)
    const int lane = tid & 31;
    const int cc   = lane >> 2;     // frag group id
    const int q    = lane & 3;

    // ---- stage encoder weights + bias + Wih ----
    stage_weights(Whi, Wlo, enc_Whh, colbase, tid);
    if (tid < NR) {
        const int g2 = tid >> 3, c2 = tid & 7;
        bias_sh[tid] = enc_b[g2 * Hn + colbase + c2];
        #pragma unroll
        for (int k = 0; k < Fn; k++)
            wih_sh[tid * Fn + k] = enc_Wih[(size_t)(g2 * Hn + colbase + c2) * Fn + k];
    }

    // ---- per-launch re-init of global scratch + counters ----
    {
        const int per = (Bn * Hn) / NBLK;   // 1024
        __nv_bfloat16* zh = &g_h_hi[1][0][0] + bid * per;
        __nv_bfloat16* zl = &g_h_lo[1][0][0] + bid * per;
        for (int j = tid; j < per; j += 256) { zh[j] = __nv_bfloat16(0.f); zl[j] = __nv_bfloat16(0.f); }
        const int pero = (Bn * Pn + NBLK - 1) / NBLK;
        const int base = bid * pero;
        for (int j = tid; j < pero; j += 256)
            if (base + j < Bn * Pn) out[base + j] = 0.0f;
        if (bid == 0 && tid < 8)
            asm volatile("st.relaxed.gpu.u32 [%0], %1;"
                         :: "l"(&g_cnt[tid >> 2][tid & 3]), "r"(0u) : "memory");
    }

    float creg[4] = {0.f, 0.f, 0.f, 0.f};
    const float lw = lin_W[colbase + cc];
    const float lb = lin_b[0];

    // ---- A ldmatrix base addresses (byte, shared space) ----
    unsigned aBase[2][2];   // [tm][plane]
    {
        const int mat  = lane >> 3;
        const int mrow = ((mat & 1) << 3) + (lane & 7);
        const int kb   = (mat >> 1) * 16;
        const unsigned whiA = (unsigned)__cvta_generic_to_shared(Whi);
        const unsigned wloA = (unsigned)__cvta_generic_to_shared(Wlo);
        #pragma unroll
        for (int tm = 0; tm < 2; tm++) {
            aBase[tm][0] = whiA + (unsigned)((16 * tm + mrow) * WPS) * 2 + kb;
            aBase[tm][1] = wloA + (unsigned)((16 * tm + mrow) * WPS) * 2 + kb;
        }
    }
    // ---- B global row offsets (elements): per tn, lane row + k phase ----
    // B frag (validated vs R7 ldsm path): n = lane>>2, b0 k = 2q,2q+1 ; b1 k = +8
    size_t bRow[2];   // [tn] element offset into g_h_* for this lane
    #pragma unroll
    for (int tn = 0; tn < 2; tn++)
        bRow[tn] = (size_t)(bstart + w * 16 + tn * 8 + (lane >> 2)) * Hn + 2 * q;

    grid_barrier();   // zeros + counters + weights visible (only full barrier)

    float bias_r[4];
    #pragma unroll
    for (int g2 = 0; g2 < 4; g2++) bias_r[g2] = bias_sh[g2 * 8 + cc];

    for (int s = 0; s < Sn + Pn; s++) {
        const bool enc = (s < Sn);
        const unsigned tgt = 16u * (unsigned)s;
        const __nv_bfloat16* hprev_hi = &g_h_hi[(s + 1) & 1][0][0];
        const __nv_bfloat16* hprev_lo = &g_h_lo[(s + 1) & 1][0][0];
        __nv_bfloat16*       hnext_hi = &g_h_hi[s & 1][0][0];
        __nv_bfloat16*       hnext_lo = &g_h_lo[s & 1][0][0];

        // ---- encoder -> decoder weight swap (once, block-local) ----
        if (s == Sn) {
            __syncthreads();
            stage_weights(Whi, Wlo, dec_Whh, colbase, tid);
            if (tid < NR) {
                const int g2 = tid >> 3, c2 = tid & 7;
                bias_sh[tid] = dec_b[g2 * Hn + colbase + c2];
                wih_sh[tid * Fn] = dec_Wih[g2 * Hn + colbase + c2];
            }
            __syncthreads();
            #pragma unroll
            for (int g2 = 0; g2 < 4; g2++) bias_r[g2] = bias_sh[g2 * 8 + cc];
        }

        // ---- accumulator init: bias + Wih*x (warp-local staging only) ----
        float d[2][2][4];
        if (enc) {
            {   // warp w stages x for its own 16 batches; no block sync needed
                const int b = w * 16 + (lane >> 1), part = lane & 1;
                const float4 v = *(const float4*)(x_enc +
                        ((size_t)(bstart + b) * Sn + s) * Fn + part * 4);
                *((float4*)&x_sh[b * Fn + part * 4]) = v;
            }
            __syncwarp();
            #pragma unroll
            for (int tn = 0; tn < 2; tn++) {
                #pragma unroll
                for (int j = 0; j < 2; j++) {
                    const int nb = w * 16 + tn * 8 + 2 * q + j;
                    float t[4];
                    #pragma unroll
                    for (int g2 = 0; g2 < 4; g2++) t[g2] = bias_r[g2];
                    #pragma unroll
                    for (int k = 0; k < Fn; k++) {
                        const float xv = x_sh[nb * Fn + k];
                        #pragma unroll
                        for (int g2 = 0; g2 < 4; g2++)
                            t[g2] = fmaf(xv, wih_sh[(g2 * 8 + cc) * Fn + k], t[g2]);
                    }
                    d[0][tn][0 + j] = t[0];
                    d[0][tn][2 + j] = t[1];
                    d[1][tn][0 + j] = t[2];
                    d[1][tn][2 + j] = t[3];
                }
            }
        } else {
            // y feedback needs ALL producers of step s-1 done
            #pragma unroll
            for (int cg = 0; cg < 4; cg++) poll_cnt(gbx, cg, tgt);
            float wv[4];
            #pragma unroll
            for (int g2 = 0; g2 < 4; g2++) wv[g2] = wih_sh[(g2 * 8 + cc) * Fn];
            #pragma unroll
            for (int tn = 0; tn < 2; tn++) {
                #pragma unroll
                for (int j = 0; j < 2; j++) {
                    const int b = bstart + w * 16 + tn * 8 + 2 * q + j;
                    const float xv = (s == Sn)
                        ? x_enc[((size_t)b * Sn + (Sn - 1)) * Fn + 3]
                        : out[(size_t)b * Pn + (s - Sn - 1)];
                    d[0][tn][0 + j] = fmaf(xv, wv[0], bias_r[0]);
                    d[0][tn][2 + j] = fmaf(xv, wv[1], bias_r[1]);
                    d[1][tn][0 + j] = fmaf(xv, wv[2], bias_r[2]);
                    d[1][tn][2 + j] = fmaf(xv, wv[3], bias_r[3]);
                }
            }
        }

        // ---- GEMM over K=512: free-running, B direct from global ----
        #pragma unroll
        for (int ci = 0; ci < 4; ci++) {
            poll_cnt(gbx, ci, tgt);       // cols [128ci,128ci+128) ready
            #pragma unroll
            for (int ktl = 0; ktl < 8; ktl++) {
                const int kt = ci * 8 + ktl;
                const unsigned kbA = (unsigned)kt * 32u;    // bytes
                const size_t   ke  = (size_t)kt * 16;       // elements

                unsigned a_hi[2][4], a_lo[2][4];
                #pragma unroll
                for (int tm = 0; tm < 2; tm++) {
                    ldsm_x4(a_hi[tm], aBase[tm][0] + kbA);
                    ldsm_x4(a_lo[tm], aBase[tm][1] + kbA);
                }
                unsigned b_hi[2][2], b_lo[2][2];
                #pragma unroll
                for (int tn = 0; tn < 2; tn++) {
                    const __nv_bfloat16* ph = hprev_hi + bRow[tn] + ke;
                    const __nv_bfloat16* pl = hprev_lo + bRow[tn] + ke;
                    b_hi[tn][0] = ldg32(ph);
                    b_hi[tn][1] = ldg32(ph + 8);
                    b_lo[tn][0] = ldg32(pl);
                    b_lo[tn][1] = ldg32(pl + 8);
                }
                #pragma unroll
                for (int tm = 0; tm < 2; tm++) {
                    #pragma unroll
                    for (int tn = 0; tn < 2; tn++) {
                        mma_bf16(d[tm][tn], a_hi[tm], b_hi[tn][0], b_hi[tn][1]);
                        mma_bf16(d[tm][tn], a_hi[tm], b_lo[tn][0], b_lo[tn][1]);
                        mma_bf16(d[tm][tn], a_lo[tm], b_hi[tn][0], b_hi[tn][1]);
                    }
                }
            }
        }

        // ---- activations, state update, h write (lane-local) ----
        float hv[4];
        #pragma unroll
        for (int tn = 0; tn < 2; tn++) {
            #pragma unroll
            for (int j = 0; j < 2; j++) {
                const int idx = 2 * tn + j;
                const float ig = sigf(d[0][tn][j]);
                const float fg = sigf(d[0][tn][2 + j]);
                const float gg = tanh_fast(d[1][tn][j]);
                const float og = sigf(d[1][tn][2 + j]);
                const float cn = fmaf(fg, creg[idx], ig * gg);
                creg[idx] = cn;
                const float h = og * tanh_fast(cn);
                hv[idx] = h;
                const int b = bstart + w * 16 + tn * 8 + 2 * q + j;
                __nv_bfloat16 hh, hl;
                split2(h, hh, hl);
                hnext_hi[(size_t)b * Hn + colbase + cc] = hh;
                hnext_lo[(size_t)b * Hn + colbase + cc] = hl;
            }
        }

        // ---- decoder output: y = h @ lin_W^T + lin_b ----
        if (!enc) {
            float py[4];
            #pragma unroll
            for (int idx = 0; idx < 4; idx++) py[idx] = hv[idx] * lw;
            #pragma unroll
            for (int off = 4; off <= 16; off <<= 1) {
                #pragma unroll
                for (int idx = 0; idx < 4; idx++)
                    py[idx] += __shfl_xor_sync(0xffffffffu, py[idx], off);
            }
            if (cc == 0) {
                const float add = (gh == 0) ? lb : 0.0f;
                #pragma unroll
                for (int tn = 0; tn < 2; tn++)
                    #pragma unroll
                    for (int j = 0; j < 2; j++) {
                        const int b = bstart + w * 16 + tn * 8 + 2 * q + j;
                        atomicAdd(&out[(size_t)b * Pn + (s - Sn)],
                                  py[2 * tn + j] + add);
                    }
            }
        }

        // ---- publish: this block's h columns (and y adds) for step s ----
        __syncthreads();
        if (tid == 0) {
            unsigned dummy;
            asm volatile("atom.add.release.gpu.u32 %0, [%1], %2;"
                         : "=r"(dummy) : "l"(&g_cnt[gbx][mygrp]), "r"(1u) : "memory");
        }
    }
}

// ---------------- launch ----------------
extern "C" void kernel_launch(void* const* d_in, const int* in_sizes, int n_in,
                              void* d_out, int out_size)
{
    const float* x_enc   = (const float*)d_in[0];
    const float* enc_Wih = (const float*)d_in[1];
    const float* enc_Whh = (const float*)d_in[2];
    const float* enc_b   = (const float*)d_in[3];
    const float* dec_Wih = (const float*)d_in[4];
    const float* dec_Whh = (const float*)d_in[5];
    const float* dec_b   = (const float*)d_in[6];
    const float* lin_W   = (const float*)d_in[7];
    const float* lin_b   = (const float*)d_in[8];
    float* out = (float*)d_out;

    cudaFuncSetAttribute(lstm_kernel,
                         cudaFuncAttributeMaxDynamicSharedMemorySize, SMEM_BYTES);

    lstm_kernel<<<NBLK, 256, SMEM_BYTES>>>(x_enc, enc_Wih, enc_Whh, enc_b,
                                           dec_Wih, dec_Whh, dec_b,
                                           lin_W, lin_b, out);
}

// round 17
// speedup vs baseline: 1.5413x; 1.3077x over previous
#include <cuda_runtime.h>
#include <cuda_bf16.h>

// ---------------- problem dims ----------------
#define Bn 256
#define Sn 336
#define Fn 8
#define Hn 512
#define Pn 96

// ---------------- partition: 4 batch quarters x 32 col groups ----------------
#define GBQ  4                 // batch quarters (64 batches each)
#define GHN  32                // col groups (16 cols each)
#define NBLK (GBQ * GHN)       // 128 blocks
#define BT   64                // batches per block
#define CT   16                // h-cols per block
#define NR   64                // gate rows per block (4 gates x 16 cols)
#define KCH  64                // k per staged chunk
#define NCH  (Hn / KCH)        // 8

// plane strides (bf16); stride*2 mod 128 == 16 -> ldmatrix phases tile banks
#define WPS 520                // W row stride
#define BPS 72                 // h row stride (64 data + 8 pad)
#define W_HALF (NR * WPS)      // 33280 bf16 per W plane
#define B_HALF (BT * BPS)      // 4608 bf16 per h plane per buffer
#define BF_TOTAL (2 * W_HALF + 4 * B_HALF)   // 84992 bf16 = 169984 B

#define XGS  65                // gate-exchange row stride (floats)
#define XG_F (NR * XGS)        // 4160
#define XS_F (BT * Fn)         // 512
#define SMEM_BYTES (BF_TOTAL * 2 + (XG_F + XS_F + NR + NR * Fn) * 4)  // 190976

// ---------------- device scratch ----------------
__device__ __nv_bfloat16 g_h_hi[2][Bn][Hn];
__device__ __nv_bfloat16 g_h_lo[2][Bn][Hn];
__device__ unsigned g_bar_count;
__device__ unsigned g_bar_gen;
__device__ unsigned g_cnt[GBQ][NCH];   // monotonic producer counters

// ---------------- helpers ----------------
__device__ __forceinline__ void cp_async16(void* dst_sh, const void* src) {
    unsigned d = (unsigned)__cvta_generic_to_shared(dst_sh);
    asm volatile("cp.async.ca.shared.global [%0], [%1], 16;\n" :: "r"(d), "l"(src));
}
__device__ __forceinline__ void cp_commit() {
    asm volatile("cp.async.commit_group;\n" ::: "memory");
}
template <int N>
__device__ __forceinline__ void cp_wait() {
    asm volatile("cp.async.wait_group %0;\n" :: "n"(N) : "memory");
}

__device__ __forceinline__ float sigf(float x) { return 1.0f / (1.0f + __expf(-x)); }
__device__ __forceinline__ float tanh_fast(float x) {
    return 2.0f / (1.0f + __expf(-2.0f * x)) - 1.0f;
}
__device__ __forceinline__ void split2(float x, __nv_bfloat16& h, __nv_bfloat16& l) {
    h = __float2bfloat16(x);
    l = __float2bfloat16(x - __bfloat162float(h));
}

__device__ __forceinline__ void mma_bf16(float d[4], const unsigned a[4],
                                         const unsigned b0, const unsigned b1) {
    asm volatile(
        "mma.sync.aligned.m16n8k16.row.col.f32.bf16.bf16.f32 "
        "{%0,%1,%2,%3},{%4,%5,%6,%7},{%8,%9},{%0,%1,%2,%3};"
        : "+f"(d[0]), "+f"(d[1]), "+f"(d[2]), "+f"(d[3])
        : "r"(a[0]), "r"(a[1]), "r"(a[2]), "r"(a[3]), "r"(b0), "r"(b1));
}
__device__ __forceinline__ void ldsm_x4(unsigned a[4], unsigned addr) {
    asm volatile("ldmatrix.sync.aligned.m8n8.x4.shared.b16 {%0,%1,%2,%3},[%4];"
                 : "=r"(a[0]), "=r"(a[1]), "=r"(a[2]), "=r"(a[3]) : "r"(addr));
}

__device__ __forceinline__ void poll_cnt(int qv, int cg, unsigned target) {
    if (target == 0u) return;
    const unsigned* a = &g_cnt[qv][cg];
    unsigned v;
    do {
        asm volatile("ld.acquire.gpu.u32 %0, [%1];" : "=r"(v) : "l"(a) : "memory");
    } while (v < target);
}

// full grid barrier (used ONCE after init)
__device__ __forceinline__ void grid_barrier() {
    __syncthreads();
    if (threadIdx.x == 0) {
        unsigned gen;
        asm volatile("ld.acquire.gpu.u32 %0, [%1];" : "=r"(gen) : "l"(&g_bar_gen) : "memory");
        unsigned prev;
        asm volatile("atom.add.release.gpu.u32 %0, [%1], 1;"
                     : "=r"(prev) : "l"(&g_bar_count) : "memory");
        if (prev == NBLK - 1) {
            asm volatile("st.relaxed.gpu.u32 [%0], %1;" :: "l"(&g_bar_count), "r"(0u) : "memory");
            asm volatile("st.release.gpu.u32 [%0], %1;" :: "l"(&g_bar_gen), "r"(gen + 1u) : "memory");
        } else {
            unsigned cur;
            do {
                asm volatile("ld.acquire.gpu.u32 %0, [%1];" : "=r"(cur) : "l"(&g_bar_gen) : "memory");
            } while (cur == gen);
        }
    }
    __syncthreads();
}

// stage 64x512 weight slice split into hi/lo planes
// smem row r = gate*16 + col  (gate = r>>4, col = r&15)
__device__ __forceinline__ void stage_weights(__nv_bfloat16* Whi, __nv_bfloat16* Wlo,
                                              const float* W, int colbase, int tid) {
    const int r    = tid >> 2;       // 0..63
    const int seg  = tid & 3;        // 128-col segment
    const int gate = r >> 4;
    const int col  = r & 15;
    const float* src = W + (size_t)(gate * Hn + colbase + col) * Hn + seg * 128;
    __nv_bfloat16* dh = Whi + r * WPS + seg * 128;
    __nv_bfloat16* dl = Wlo + r * WPS + seg * 128;
    #pragma unroll
    for (int j = 0; j < 32; j++) {
        const float4 v = ((const float4*)src)[j];
        split2(v.x, dh[4 * j + 0], dl[4 * j + 0]);
        split2(v.y, dh[4 * j + 1], dl[4 * j + 1]);
        split2(v.z, dh[4 * j + 2], dl[4 * j + 2]);
        split2(v.w, dh[4 * j + 3], dl[4 * j + 3]);
    }
}

// ---------------- kernel ----------------
__global__ void __launch_bounds__(256, 1)
lstm_kernel(const float* __restrict__ x_enc,
            const float* __restrict__ enc_Wih,
            const float* __restrict__ enc_Whh,
            const float* __restrict__ enc_b,
            const float* __restrict__ dec_Wih,
            const float* __restrict__ dec_Whh,
            const float* __restrict__ dec_b,
            const float* __restrict__ lin_W,
            const float* __restrict__ lin_b,
            float* __restrict__ out)
{
    extern __shared__ __nv_bfloat16 smem_bf[];
    __nv_bfloat16* Whi = smem_bf;                      // [NR][WPS]
    __nv_bfloat16* Wlo = Whi + W_HALF;                 // [NR][WPS]
    __nv_bfloat16* Bsh = Wlo + W_HALF;                 // [2 buf][2 plane][BT][BPS]
    float* xg      = (float*)(smem_bf + BF_TOTAL);     // [NR][XGS] gate exchange
    float* x_sh    = xg + XG_F;                        // [BT][Fn]
    float* bias_sh = x_sh + XS_F;                      // [NR] (gate*16+col)
    float* wih_sh  = bias_sh + NR;                     // [NR][Fn]

    const int tid     = threadIdx.x;
    const int bid     = blockIdx.x;
    const int gh      = bid % GHN;      // col group 0..31
    const int gbq     = bid / GHN;      // batch quarter 0..3
    const int bstart  = gbq * BT;
    const int colbase = gh * CT;
    const int mygrp   = gh >> 2;        // chunk group produced (0..7)

    const int w    = tid >> 5;          // warp 0..7
    const int lane = tid & 31;
    const int wg   = w & 3;             // gate (A tile rows wg*16..+15)
    const int wb   = w >> 2;            // batch half (batches wb*32..+31)
    const int cc   = lane >> 2;
    const int q    = lane & 3;

    // ---- stage encoder weights + bias + Wih ----
    stage_weights(Whi, Wlo, enc_Whh, colbase, tid);
    if (tid < NR) {
        const int g2 = tid >> 4, c2 = tid & 15;
        bias_sh[tid] = enc_b[g2 * Hn + colbase + c2];
        #pragma unroll
        for (int k = 0; k < Fn; k++)
            wih_sh[tid * Fn + k] = enc_Wih[(size_t)(g2 * Hn + colbase + c2) * Fn + k];
    }

    // ---- per-launch re-init of global scratch + counters ----
    {
        const int per = (Bn * Hn) / NBLK;   // 1024
        __nv_bfloat16* zh = &g_h_hi[1][0][0] + bid * per;
        __nv_bfloat16* zl = &g_h_lo[1][0][0] + bid * per;
        for (int j = tid; j < per; j += 256) { zh[j] = __nv_bfloat16(0.f); zl[j] = __nv_bfloat16(0.f); }
        const int pero = (Bn * Pn) / NBLK;  // 192
        const int base = bid * pero;
        for (int j = tid; j < pero; j += 256) out[base + j] = 0.0f;
        if (bid == 0 && tid < GBQ * NCH)
            asm volatile("st.relaxed.gpu.u32 [%0], %1;"
                         :: "l"(&g_cnt[tid >> 3][tid & 7]), "r"(0u) : "memory");
    }

    // ---- epilogue thread mapping: (col, 4 batches) ----
    const int ecol = tid & 15;          // 0..15
    const int ebq  = tid >> 4;          // 0..15 -> batches 4*ebq..+3
    float creg[4] = {0.f, 0.f, 0.f, 0.f};
    const float lw = lin_W[colbase + ecol];
    const float lb = lin_b[0];

    // ---- ldmatrix base addresses ----
    unsigned aBase[2];   // [plane]
    {
        const int mat  = lane >> 3;
        const int mrow = wg * 16 + ((mat & 1) << 3) + (lane & 7);
        const int kb   = (mat >> 1) * 16;
        aBase[0] = (unsigned)__cvta_generic_to_shared(Whi) + (unsigned)(mrow * WPS) * 2 + kb;
        aBase[1] = (unsigned)__cvta_generic_to_shared(Wlo) + (unsigned)(mrow * WPS) * 2 + kb;
    }
    unsigned bBase[2][2];   // [p2 (16-batch pair)][plane], buffer 0
    {
        const int nrow = (lane & 7) + ((lane >> 4) << 3);
        const int kb   = ((lane >> 3) & 1) * 16;
        const unsigned bA = (unsigned)__cvta_generic_to_shared(Bsh);
        #pragma unroll
        for (int p2 = 0; p2 < 2; p2++)
            #pragma unroll
            for (int p = 0; p < 2; p++)
                bBase[p2][p] = bA + (unsigned)(p * B_HALF
                               + (wb * 32 + p2 * 16 + nrow) * BPS) * 2 + kb;
    }

    grid_barrier();   // zeros + counters + weights visible

    // epilogue per-thread constants
    float bias4[4], wihv[4][Fn];
    #pragma unroll
    for (int g2 = 0; g2 < 4; g2++) {
        bias4[g2] = bias_sh[g2 * 16 + ecol];
        #pragma unroll
        for (int k = 0; k < Fn; k++) wihv[g2][k] = wih_sh[(g2 * 16 + ecol) * Fn + k];
    }

    for (int s = 0; s < Sn + Pn; s++) {
        const bool enc = (s < Sn);
        const unsigned tgt = 4u * (unsigned)s;
        const __nv_bfloat16* hprev_hi = &g_h_hi[(s + 1) & 1][0][0];
        const __nv_bfloat16* hprev_lo = &g_h_lo[(s + 1) & 1][0][0];
        __nv_bfloat16*       hnext_hi = &g_h_hi[s & 1][0][0];
        __nv_bfloat16*       hnext_lo = &g_h_lo[s & 1][0][0];

        // ---- encoder -> decoder weight swap (once, block-local) ----
        if (s == Sn) {
            __syncthreads();
            stage_weights(Whi, Wlo, dec_Whh, colbase, tid);
            if (tid < NR) {
                const int g2 = tid >> 4, c2 = tid & 15;
                bias_sh[tid] = dec_b[g2 * Hn + colbase + c2];
                wih_sh[tid * Fn] = dec_Wih[g2 * Hn + colbase + c2];
            }
            __syncthreads();
            #pragma unroll
            for (int g2 = 0; g2 < 4; g2++) {
                bias4[g2] = bias_sh[g2 * 16 + ecol];
                wihv[g2][0] = wih_sh[(g2 * 16 + ecol) * Fn];
            }
        }

        // ---- stage x_t (encoder) ----
        if (enc && tid < 128) {
            const int b = tid >> 1, part = tid & 1;
            const float4 v = *(const float4*)(x_enc +
                    ((size_t)(bstart + b) * Sn + s) * Fn + part * 4);
            *((float4*)&x_sh[b * Fn + part * 4]) = v;
        }

        // ---- prefetch chunk 0 ----
        poll_cnt(gbq, 0, tgt);
        {
            #pragma unroll
            for (int j = 0; j < 4; j++) {
                const int idx   = j * 256 + tid;     // 1024 x 16B per chunk
                const int plane = idx >> 9;
                const int rem   = idx & 511;
                const int row   = rem >> 3;
                const int seg   = rem & 7;
                const __nv_bfloat16* sp = plane ? hprev_lo : hprev_hi;
                cp_async16(Bsh + plane * B_HALF + row * BPS + seg * 8,
                           sp + (size_t)(bstart + row) * Hn + seg * 8);
            }
            cp_commit();
        }

        // ---- accumulators start at zero (xinit added in epilogue) ----
        float d[4][4];
        #pragma unroll
        for (int tn = 0; tn < 4; tn++)
            #pragma unroll
            for (int r = 0; r < 4; r++) d[tn][r] = 0.0f;

        // ---- GEMM over K=512, 8 chunks, double-buffered ----
        for (int ci = 0; ci < NCH; ci++) {
            __syncthreads();
            if (ci + 1 < NCH) {
                poll_cnt(gbq, ci + 1, tgt);
                __nv_bfloat16* dst = Bsh + ((ci + 1) & 1) * (2 * B_HALF);
                const int koff = (ci + 1) * KCH;
                #pragma unroll
                for (int j = 0; j < 4; j++) {
                    const int idx   = j * 256 + tid;
                    const int plane = idx >> 9;
                    const int rem   = idx & 511;
                    const int row   = rem >> 3;
                    const int seg   = rem & 7;
                    const __nv_bfloat16* sp = plane ? hprev_lo : hprev_hi;
                    cp_async16(dst + plane * B_HALF + row * BPS + seg * 8,
                               sp + (size_t)(bstart + row) * Hn + koff + seg * 8);
                }
                cp_commit();
                cp_wait<1>();
            } else {
                cp_wait<0>();
            }
            __syncthreads();

            const unsigned bufOff = (unsigned)((ci & 1) * (2 * B_HALF)) * 2;
            #pragma unroll
            for (int kt = 0; kt < KCH / 16; kt++) {        // 4 k16 steps
                const unsigned kbA = (unsigned)(ci * KCH + kt * 16) * 2;
                const unsigned kbB = bufOff + (unsigned)(kt * 16) * 2;

                unsigned a_hi[4], a_lo[4];
                ldsm_x4(a_hi, aBase[0] + kbA);
                ldsm_x4(a_lo, aBase[1] + kbA);
                unsigned b_hi[2][4], b_lo[2][4];
                #pragma unroll
                for (int p2 = 0; p2 < 2; p2++) {
                    ldsm_x4(b_hi[p2], bBase[p2][0] + kbB);
                    ldsm_x4(b_lo[p2], bBase[p2][1] + kbB);
                }
                #pragma unroll
                for (int tn = 0; tn < 4; tn++) {
                    const int p2 = tn >> 1, sub = tn & 1;
                    mma_bf16(d[tn], a_hi, b_hi[p2][2 * sub], b_hi[p2][2 * sub + 1]);
                    mma_bf16(d[tn], a_hi, b_lo[p2][2 * sub], b_lo[p2][2 * sub + 1]);
                    mma_bf16(d[tn], a_lo, b_hi[p2][2 * sub], b_hi[p2][2 * sub + 1]);
                }
            }
        }

        // ---- store D frags to gate-exchange buffer ----
        #pragma unroll
        for (int tn = 0; tn < 4; tn++) {
            const int b0 = wb * 32 + tn * 8 + 2 * q;
            float* x0 = xg + (wg * 16 + cc) * XGS + b0;
            float* x1 = xg + (wg * 16 + cc + 8) * XGS + b0;
            x0[0] = d[tn][0]; x0[1] = d[tn][1];
            x1[0] = d[tn][2]; x1[1] = d[tn][3];
        }
        __syncthreads();

        // ---- epilogue: thread = (ecol, batches 4*ebq..+3) ----
        float py[4];
        #pragma unroll
        for (int j = 0; j < 4; j++) {
            const int bb = 4 * ebq + j;
            float g4[4];
            if (enc) {
                #pragma unroll
                for (int g2 = 0; g2 < 4; g2++) {
                    float t = bias4[g2];
                    #pragma unroll
                    for (int k = 0; k < Fn; k++)
                        t = fmaf(x_sh[bb * Fn + k], wihv[g2][k], t);
                    g4[g2] = t;
                }
            } else {
                const int b = bstart + bb;
                const float xv = (s == Sn)
                    ? x_enc[((size_t)b * Sn + (Sn - 1)) * Fn + 3]
                    : out[(size_t)b * Pn + (s - Sn - 1)];
                #pragma unroll
                for (int g2 = 0; g2 < 4; g2++)
                    g4[g2] = fmaf(xv, wihv[g2][0], bias4[g2]);
            }
            #pragma unroll
            for (int g2 = 0; g2 < 4; g2++)
                g4[g2] += xg[(g2 * 16 + ecol) * XGS + bb];

            const float ig = sigf(g4[0]);
            const float fg = sigf(g4[1]);
            const float gg = tanh_fast(g4[2]);
            const float og = sigf(g4[3]);
            const float cn = fmaf(fg, creg[j], ig * gg);
            creg[j] = cn;
            const float h = og * tanh_fast(cn);
            py[j] = h * lw;
            __nv_bfloat16 hh, hl;
            split2(h, hh, hl);
            const size_t off = (size_t)(bstart + bb) * Hn + colbase + ecol;
            hnext_hi[off] = hh;
            hnext_lo[off] = hl;
        }

        // ---- decoder output ----
        if (!enc) {
            #pragma unroll
            for (int off2 = 1; off2 <= 8; off2 <<= 1) {
                #pragma unroll
                for (int j = 0; j < 4; j++)
                    py[j] += __shfl_xor_sync(0xffffffffu, py[j], off2, 16);
            }
            if (ecol == 0) {
                const float add = (gh == 0) ? lb : 0.0f;
                #pragma unroll
                for (int j = 0; j < 4; j++)
                    atomicAdd(&out[(size_t)(bstart + 4 * ebq + j) * Pn + (s - Sn)],
                              py[j] + add);
            }
        }

        // ---- publish this block's columns for step s ----
        __syncthreads();
        if (tid == 0) {
            unsigned dummy;
            asm volatile("atom.add.release.gpu.u32 %0, [%1], %2;"
                         : "=r"(dummy) : "l"(&g_cnt[gbq][mygrp]), "r"(1u) : "memory");
        }
    }
}

// ---------------- launch ----------------
extern "C" void kernel_launch(void* const* d_in, const int* in_sizes, int n_in,
                              void* d_out, int out_size)
{
    const float* x_enc   = (const float*)d_in[0];
    const float* enc_Wih = (const float*)d_in[1];
    const float* enc_Whh = (const float*)d_in[2];
    const float* enc_b   = (const float*)d_in[3];
    const float* dec_Wih = (const float*)d_in[4];
    const float* dec_Whh = (const float*)d_in[5];
    const float* dec_b   = (const float*)d_in[6];
    const float* lin_W   = (const float*)d_in[7];
    const float* lin_b   = (const float*)d_in[8];
    float* out = (float*)d_out;

    cudaFuncSetAttribute(lstm_kernel,
                         cudaFuncAttributeMaxDynamicSharedMemorySize, SMEM_BYTES);

    lstm_kernel<<<NBLK, 256, SMEM_BYTES>>>(x_enc, enc_Wih, enc_Whh, enc_b,
                                           dec_Wih, dec_Whh, dec_b,
                                           lin_W, lin_b, out);
}